// round 11
// baseline (speedup 1.0000x reference)
#include <cuda_runtime.h>
#include <cuda_fp16.h>
#include <cstdint>

// Problem dims
#define BATCH   8192
#define CH_H    2048
#define DIM     6144
#define CHUNK   512
#define NCHUNK  12
#define EPSBN   1e-5f
#define SPLITS  64

// GEMM tiling (128x128 tile, 3-stage, 2 CTAs/SM, single-pass fp16)
#define BM 128
#define BN 128
#define STAGES 3
#define MAT_BYTES 16384
#define STAGE_BYTES (2 * MAT_BYTES)        // Ah, Bh = 32768
#define SMEM_GEMM (STAGES * STAGE_BYTES)   // 98304 -> 2 CTAs/SM

// GEMM modes
#define M_BIAS      0   // store + bias
#define M_BIASRELU  1   // store + bias + relu
#define M_SPLIT     2   // split-K: plain store to C + z*BATCH*N, no bias
#define M_STATS     3   // plain store + fused column sum/sumsq partials
#define M_PACK      4   // bias + relu + dual write (fp32 C and fp16 Cp)

// ---------------- scratch ----------------
__device__ float g_buf[2 * (size_t)BATCH * CH_H];   // contiguous: halves for split-K
__device__ float g_psum[SPLITS * CH_H];
__device__ float g_psq [SPLITS * CH_H];
__device__ float g_scale[CH_H];
__device__ float g_shift[CH_H];
__device__ __half g_Ah[(size_t)BATCH * DIM];
__device__ __half g_Ah2[(size_t)BATCH * CH_H];      // layer-3 packed output (no aliasing)
__device__ __half g_Bh[(size_t)DIM * CH_H];

// ---------------- helpers ----------------
__device__ __forceinline__ uint32_t smem_u32(const void* p) {
    uint32_t a;
    asm("{ .reg .u64 t; cvta.to.shared.u64 t, %1; cvt.u32.u64 %0, t; }" : "=r"(a) : "l"(p));
    return a;
}
__device__ __forceinline__ void cp16(uint32_t s, const void* g) {
    asm volatile("cp.async.cg.shared.global [%0], [%1], 16;" :: "r"(s), "l"(g));
}
#define CP_COMMIT() asm volatile("cp.async.commit_group;" ::: "memory")
#define CP_WAIT1()  asm volatile("cp.async.wait_group 1;" ::: "memory")

__device__ __forceinline__ void ldmx4(uint32_t* r, uint32_t addr) {
    asm volatile("ldmatrix.sync.aligned.m8n8.x4.shared.b16 {%0,%1,%2,%3}, [%4];"
                 : "=r"(r[0]), "=r"(r[1]), "=r"(r[2]), "=r"(r[3]) : "r"(addr));
}
__device__ __forceinline__ void mma16816(float* d, const uint32_t* a, const uint32_t* b) {
    asm volatile("mma.sync.aligned.m16n8k16.row.col.f32.f16.f16.f32 "
                 "{%0,%1,%2,%3}, {%4,%5,%6,%7}, {%8,%9}, {%0,%1,%2,%3};"
                 : "+f"(d[0]), "+f"(d[1]), "+f"(d[2]), "+f"(d[3])
                 : "r"(a[0]), "r"(a[1]), "r"(a[2]), "r"(a[3]), "r"(b[0]), "r"(b[1]));
}
__device__ __forceinline__ uint32_t pack2h(float f0, float f1) {
    __half h0 = __float2half_rn(f0);
    __half h1 = __float2half_rn(f1);
    return (uint32_t)__half_as_ushort(h0) | ((uint32_t)__half_as_ushort(h1) << 16);
}

// ---------------- score + reweight + pack A (layer-1 input) ----------------
__global__ __launch_bounds__(512) void score_pack(
    const float* __restrict__ ft0, const float* __restrict__ ft1,
    const float* __restrict__ ft2, const float* __restrict__ key,
    float* __restrict__ ft_all, __half* __restrict__ Ah)
{
    const int row = blockIdx.x, t = threadIdx.x;
    const int warp = t >> 5, lane = t & 31;
    __shared__ float wsum[16];
    __shared__ float sc[NCHUNK];
    const float kv = key[t];
    float x[NCHUNK];
#pragma unroll
    for (int c = 0; c < NCHUNK; ++c) {
        const float* src = (c < 4) ? ft0 : ((c < 8) ? ft1 : ft2);
        x[c] = src[(size_t)row * CH_H + (c & 3) * CHUNK + t];
    }
#pragma unroll
    for (int c = 0; c < NCHUNK; ++c) {
        float p = x[c] * kv;
#pragma unroll
        for (int o = 16; o; o >>= 1) p += __shfl_xor_sync(0xffffffffu, p, o);
        if (lane == 0) wsum[warp] = p;
        __syncthreads();
        if (warp == 0) {
            float q = (lane < 16) ? wsum[lane] : 0.f;
#pragma unroll
            for (int o = 8; o; o >>= 1) q += __shfl_xor_sync(0xffffffffu, q, o);
            if (lane == 0) sc[c] = q;
        }
        __syncthreads();
    }
    float mx = sc[0];
#pragma unroll
    for (int c = 1; c < NCHUNK; ++c) mx = fmaxf(mx, sc[c]);
    float e[NCHUNK], s = 0.f;
#pragma unroll
    for (int c = 0; c < NCHUNK; ++c) { e[c] = expf(sc[c] - mx); s += e[c]; }
    const float inv = 1.0f / s;
#pragma unroll
    for (int c = 0; c < NCHUNK; ++c) {
        float v = x[c] * (1.0f + e[c] * inv);
        size_t idx = (size_t)row * DIM + c * CHUNK + t;
        ft_all[idx] = v;
        Ah[idx] = __float2half_rn(v);
    }
}

// ---------------- BN apply + pack (single input) ----------------
__global__ __launch_bounds__(256) void bn_pack(
    const float* __restrict__ Y, __half* __restrict__ Ah, int K)
{
    size_t i = ((size_t)blockIdx.x * 256 + threadIdx.x) * 8;
    int col = (int)(i % K);
    float4 y0 = *(const float4*)(Y + i);
    float4 y1 = *(const float4*)(Y + i + 4);
    float4 s0 = *(const float4*)(g_scale + col);
    float4 s1 = *(const float4*)(g_scale + col + 4);
    float4 h0 = *(const float4*)(g_shift + col);
    float4 h1 = *(const float4*)(g_shift + col + 4);
    uint4 hp;
    hp.x = pack2h(fmaf(y0.x, s0.x, h0.x), fmaf(y0.y, s0.y, h0.y));
    hp.y = pack2h(fmaf(y0.z, s0.z, h0.z), fmaf(y0.w, s0.w, h0.w));
    hp.z = pack2h(fmaf(y1.x, s1.x, h1.x), fmaf(y1.y, s1.y, h1.y));
    hp.w = pack2h(fmaf(y1.z, s1.z, h1.z), fmaf(y1.w, s1.w, h1.w));
    *(uint4*)((char*)Ah + i * 2) = hp;
}

// ---------------- BN apply + pack (sum of the two split-K halves) --------------
__global__ __launch_bounds__(256) void bn_pack2(
    const float* __restrict__ YA, const float* __restrict__ YB,
    __half* __restrict__ Ah, int K)
{
    size_t i = ((size_t)blockIdx.x * 256 + threadIdx.x) * 8;
    int col = (int)(i % K);
    float4 a0 = *(const float4*)(YA + i);
    float4 a1 = *(const float4*)(YA + i + 4);
    float4 b0 = *(const float4*)(YB + i);
    float4 b1 = *(const float4*)(YB + i + 4);
    float4 s0 = *(const float4*)(g_scale + col);
    float4 s1 = *(const float4*)(g_scale + col + 4);
    float4 h0 = *(const float4*)(g_shift + col);
    float4 h1 = *(const float4*)(g_shift + col + 4);
    uint4 hp;
    hp.x = pack2h(fmaf(a0.x + b0.x, s0.x, h0.x), fmaf(a0.y + b0.y, s0.y, h0.y));
    hp.y = pack2h(fmaf(a0.z + b0.z, s0.z, h0.z), fmaf(a0.w + b0.w, s0.w, h0.w));
    hp.z = pack2h(fmaf(a1.x + b1.x, s1.x, h1.x), fmaf(a1.y + b1.y, s1.y, h1.y));
    hp.w = pack2h(fmaf(a1.z + b1.z, s1.z, h1.z), fmaf(a1.w + b1.w, s1.w, h1.w));
    *(uint4*)((char*)Ah + i * 2) = hp;
}

// ---------------- pack W: fp32 [K,N] -> fp16 [N,K] (transpose) ----------
__global__ __launch_bounds__(256) void pack_W_t(
    const float* __restrict__ W, __half* __restrict__ Bh, int K, int N)
{
    __shared__ float sm[32][33];
    const int k0 = blockIdx.x * 32, n0 = blockIdx.y * 32;
    const int tx = threadIdx.x & 31, ty = threadIdx.x >> 5;
#pragma unroll
    for (int i = 0; i < 4; ++i)
        sm[ty + 8 * i][tx] = W[(size_t)(k0 + ty + 8 * i) * N + n0 + tx];
    __syncthreads();
    const int kp = threadIdx.x & 15;
    const int nb = threadIdx.x >> 4;
#pragma unroll
    for (int j = 0; j < 2; ++j) {
        int n = nb + j * 16;
        *(uint32_t*)&Bh[(size_t)(n0 + n) * K + k0 + kp * 2] =
            pack2h(sm[kp * 2][n], sm[kp * 2 + 1][n]);
    }
}

// ---------------- mma.sync GEMM: fp16 single-pass, modal epilogue -------------
template <int MODE>
__global__ __launch_bounds__(256, 2) void gemm_mma(
    const __half* __restrict__ Ah, const __half* __restrict__ Bh,
    const float* __restrict__ bias, float* __restrict__ C,
    __half* __restrict__ Cp, int N, int Ks, int Kl)
{
    extern __shared__ __align__(128) char smem[];
    const uint32_t sb = smem_u32(smem);
    const int tid = threadIdx.x, lane = tid & 31, wid = tid >> 5;
    const int wm = wid & 1, wn = wid >> 1;
    const int m0 = blockIdx.y * BM, n0 = blockIdx.x * BN;
    const int kOff = (MODE == M_SPLIT) ? blockIdx.z * Kl : 0;
    const int KT = Kl >> 6;

    const __half* g0 = Ah + (size_t)m0 * Ks + kOff;
    const __half* g1 = Bh + (size_t)n0 * Ks + kOff;
    float* Cz = (MODE == M_SPLIT) ? C + (size_t)blockIdx.z * BATCH * N : C;

    float acc[4][4][4];
#pragma unroll
    for (int a = 0; a < 4; ++a)
#pragma unroll
        for (int b = 0; b < 4; ++b)
#pragma unroll
            for (int c = 0; c < 4; ++c) acc[a][b][c] = 0.f;

    auto load_stage = [&](int slot, int kt) {
        const uint32_t st = sb + slot * STAGE_BYTES;
        const int k0 = kt << 6;
        const __half* gs[2] = {g0, g1};
#pragma unroll
        for (int mtx = 0; mtx < 2; ++mtx) {
            const uint32_t base = st + mtx * MAT_BYTES;
            const __half* g = gs[mtx];
#pragma unroll
            for (int i = 0; i < 4; ++i) {
                int q = tid + i * 256;
                int row = q >> 3, c = q & 7;
                uint32_t sa = base + (((row << 3) + (c ^ (row & 7))) << 4);
                cp16(sa, g + (size_t)row * Ks + k0 + c * 8);
            }
        }
    };

    load_stage(0, 0); CP_COMMIT();
    load_stage(1, 1); CP_COMMIT();

    int slot = 0;
    for (int kt = 0; kt < KT; ++kt) {
        CP_WAIT1();
        __syncthreads();

        int nk = kt + 2;
        if (nk < KT) {
            int ns = slot + 2; if (ns >= STAGES) ns -= STAGES;
            load_stage(ns, nk);
            CP_COMMIT();
        }

        const uint32_t st = sb + slot * STAGE_BYTES;
#pragma unroll
        for (int kk = 0; kk < 4; ++kk) {
            const int cA = (kk << 1) + (lane >> 4);
            uint32_t bfr[4][2], afr[4][4];
#pragma unroll
            for (int half = 0; half < 2; ++half) {
                int row = wn * 32 + half * 16 + (lane & 15);
                uint32_t ad = st + MAT_BYTES + (((row << 3) + (cA ^ (row & 7))) << 4);
                uint32_t r[4];
                ldmx4(r, ad);
                bfr[half * 2][0] = r[0]; bfr[half * 2][1] = r[2];
                bfr[half * 2 + 1][0] = r[1]; bfr[half * 2 + 1][1] = r[3];
            }
#pragma unroll
            for (int mi = 0; mi < 4; ++mi) {
                int row = wm * 64 + mi * 16 + (lane & 15);
                ldmx4(afr[mi], st + (((row << 3) + (cA ^ (row & 7))) << 4));
            }
#pragma unroll
            for (int mi = 0; mi < 4; ++mi)
#pragma unroll
                for (int ni = 0; ni < 4; ++ni)
                    mma16816(acc[mi][ni], afr[mi], bfr[ni]);
        }

        if (++slot >= STAGES) slot = 0;
    }

    // ---------------- store epilogue ----------------
    const int gro = lane >> 2, t4 = lane & 3;
    const int colb = n0 + wn * 32 + t4 * 2;
#pragma unroll
    for (int mi = 0; mi < 4; ++mi) {
#pragma unroll
        for (int half = 0; half < 2; ++half) {
            int r = m0 + wm * 64 + mi * 16 + gro + half * 8;
            float* crow = Cz + (size_t)r * N;
#pragma unroll
            for (int ni = 0; ni < 4; ++ni) {
                int col = colb + ni * 8;
                float x = acc[mi][ni][half * 2 + 0];
                float y = acc[mi][ni][half * 2 + 1];
                if (MODE == M_BIAS || MODE == M_BIASRELU || MODE == M_PACK) {
                    x += bias[col]; y += bias[col + 1];
                }
                if (MODE == M_BIASRELU || MODE == M_PACK) {
                    x = fmaxf(x, 0.f); y = fmaxf(y, 0.f);
                }
                *(float2*)(crow + col) = make_float2(x, y);
                if (MODE == M_PACK) {
                    __half* prow = Cp + (size_t)r * N;
                    *(__half2*)(prow + col) = __floats2half2_rn(x, y);
                }
            }
        }
    }

    // ---------------- fused BN column-stats partials ----------------
    if (MODE == M_STATS) {
        float s[8], q[8];
#pragma unroll
        for (int ni = 0; ni < 4; ++ni)
#pragma unroll
            for (int j = 0; j < 2; ++j) {
                float ss = 0.f, qq = 0.f;
#pragma unroll
                for (int mi = 0; mi < 4; ++mi)
#pragma unroll
                    for (int half = 0; half < 2; ++half) {
                        float v = acc[mi][ni][half * 2 + j];
                        ss += v; qq = fmaf(v, v, qq);
                    }
                s[ni * 2 + j] = ss; q[ni * 2 + j] = qq;
            }
        // reduce over gro (lane bits 2..4)
#pragma unroll
        for (int m = 4; m <= 16; m <<= 1)
#pragma unroll
            for (int t = 0; t < 8; ++t) {
                s[t] += __shfl_xor_sync(0xffffffffu, s[t], m);
                q[t] += __shfl_xor_sync(0xffffffffu, q[t], m);
            }
        __syncthreads();                    // stage smem now reusable
        float* sm_s = (float*)smem;         // [2][128]
        float* sm_q = sm_s + 256;
        if (lane < 4) {                     // gro == 0, t4 == lane
#pragma unroll
            for (int ni = 0; ni < 4; ++ni)
#pragma unroll
                for (int j = 0; j < 2; ++j) {
                    int c = wn * 32 + lane * 2 + ni * 8 + j;
                    sm_s[wm * 128 + c] = s[ni * 2 + j];
                    sm_q[wm * 128 + c] = q[ni * 2 + j];
                }
        }
        __syncthreads();
        if (tid < 128) {
            g_psum[blockIdx.y * N + n0 + tid] = sm_s[tid] + sm_s[128 + tid];
            g_psq [blockIdx.y * N + n0 + tid] = sm_q[tid] + sm_q[128 + tid];
        }
    }
}

// ---------------- BN stats from the two split-K halves ----------------
__global__ __launch_bounds__(256) void colstats_partial2(
    const float* __restrict__ A, const float* __restrict__ B,
    int N, int rowsPerBlk)
{
    const int c = blockIdx.x * blockDim.x + threadIdx.x;
    const int r0 = blockIdx.y * rowsPerBlk;
    float s = 0.f, q = 0.f;
    for (int r = r0; r < r0 + rowsPerBlk; ++r) {
        float v = A[(size_t)r * N + c] + B[(size_t)r * N + c];
        s += v; q = fmaf(v, v, q);
    }
    g_psum[blockIdx.y * N + c] = s;
    g_psq [blockIdx.y * N + c] = q;
}
__global__ __launch_bounds__(256) void colstats_final(
    const float* __restrict__ g, const float* __restrict__ beta, int N, float invM)
{
    const int c = blockIdx.x * blockDim.x + threadIdx.x;
    float s = 0.f, q = 0.f;
#pragma unroll 4
    for (int i = 0; i < SPLITS; ++i) { s += g_psum[i * N + c]; q += g_psq[i * N + c]; }
    float m = s * invM;
    float v = q * invM - m * m;
    float sc = g[c] * rsqrtf(v + EPSBN);
    g_scale[c] = sc;
    g_shift[c] = beta[c] - m * sc;
}

// ---------------- launch ----------------
extern "C" void kernel_launch(void* const* d_in, const int* in_sizes, int n_in,
                              void* d_out, int out_size)
{
    const float* ft0   = (const float*)d_in[1];
    const float* ft1   = (const float*)d_in[2];
    const float* ft2   = (const float*)d_in[3];
    const float* key   = (const float*)d_in[4];
    const float* W1    = (const float*)d_in[5];
    const float* g1    = (const float*)d_in[7];
    const float* beta1 = (const float*)d_in[8];
    const float* W2    = (const float*)d_in[9];
    const float* g2    = (const float*)d_in[11];
    const float* beta2 = (const float*)d_in[12];
    const float* W3    = (const float*)d_in[13];
    const float* b3    = (const float*)d_in[14];
    const float* We    = (const float*)d_in[15];
    const float* bE    = (const float*)d_in[16];

    float* out     = (float*)d_out;
    float* aligned = out;
    float* extend  = aligned + (size_t)BATCH * CH_H;
    float* ftall   = extend  + (size_t)BATCH * DIM;

    float* buf;
    __half *Ah, *Ah2, *Bh;
    cudaGetSymbolAddress((void**)&buf, g_buf);
    cudaGetSymbolAddress((void**)&Ah, g_Ah);
    cudaGetSymbolAddress((void**)&Ah2, g_Ah2);
    cudaGetSymbolAddress((void**)&Bh, g_Bh);
    float* bufA = buf;
    float* bufB = buf + (size_t)BATCH * CH_H;   // contiguous second half (split-K z=1)

    cudaFuncSetAttribute(gemm_mma<M_BIASRELU>, cudaFuncAttributeMaxDynamicSharedMemorySize, SMEM_GEMM);
    cudaFuncSetAttribute(gemm_mma<M_SPLIT>,    cudaFuncAttributeMaxDynamicSharedMemorySize, SMEM_GEMM);
    cudaFuncSetAttribute(gemm_mma<M_STATS>,    cudaFuncAttributeMaxDynamicSharedMemorySize, SMEM_GEMM);
    cudaFuncSetAttribute(gemm_mma<M_PACK>,     cudaFuncAttributeMaxDynamicSharedMemorySize, SMEM_GEMM);

    const int MT = BATCH / BM;                    // 64
    const int PB = BATCH * CH_H / 8 / 256;        // pack blocks

    // 1) score + reweight + pack A1
    score_pack<<<BATCH, 512>>>(ft0, ft1, ft2, key, ftall, Ah);

    // 2) layer 1 (K=6144): split-K=2 into contiguous halves; bias cancels in BN
    pack_W_t<<<dim3(DIM / 32, CH_H / 32), 256>>>(W1, Bh, DIM, CH_H);
    gemm_mma<M_SPLIT><<<dim3(CH_H / BN, MT, 2), 256, SMEM_GEMM>>>(
        Ah, Bh, nullptr, bufA, nullptr, CH_H, DIM, DIM / 2);
    colstats_partial2<<<dim3(CH_H / 256, SPLITS), 256>>>(bufA, bufB, CH_H, BATCH / SPLITS);
    colstats_final<<<CH_H / 256, 256>>>(g1, beta1, CH_H, 1.0f / BATCH);
    bn_pack2<<<PB, 256>>>(bufA, bufB, Ah, CH_H);

    // 3) layer 2 (K=2048): stats fused in epilogue; bias cancels in BN
    pack_W_t<<<dim3(CH_H / 32, CH_H / 32), 256>>>(W2, Bh, CH_H, CH_H);
    gemm_mma<M_STATS><<<dim3(CH_H / BN, MT), 256, SMEM_GEMM>>>(
        Ah, Bh, nullptr, bufA, nullptr, CH_H, CH_H, CH_H);
    colstats_final<<<CH_H / 256, 256>>>(g2, beta2, CH_H, 1.0f / BATCH);
    bn_pack<<<PB, 256>>>(bufA, Ah, CH_H);

    // 4) layer 3: bias+relu epilogue, dual write fp32 'aligned' + fp16 Ah2 (no alias)
    pack_W_t<<<dim3(CH_H / 32, CH_H / 32), 256>>>(W3, Bh, CH_H, CH_H);
    gemm_mma<M_PACK><<<dim3(CH_H / BN, MT), 256, SMEM_GEMM>>>(
        Ah, Bh, b3, aligned, Ah2, CH_H, CH_H, CH_H);

    // 5) extend = relu(aligned @ We + bE), input = Ah2
    pack_W_t<<<dim3(CH_H / 32, DIM / 32), 256>>>(We, Bh, CH_H, DIM);
    gemm_mma<M_BIASRELU><<<dim3(DIM / BN, MT), 256, SMEM_GEMM>>>(
        Ah2, Bh, bE, extend, nullptr, DIM, CH_H, CH_H);
}

// round 12
// speedup vs baseline: 1.0293x; 1.0293x over previous
#include <cuda_runtime.h>
#include <cuda_fp16.h>
#include <cstdint>

// Problem dims
#define BATCH   8192
#define CH_H    2048
#define DIM     6144
#define CHUNK   512
#define NCHUNK  12
#define EPSBN   1e-5f
#define SPLITS  64

// GEMM tiling (128x128 tile, 3-stage, 2 CTAs/SM, single-pass fp16)
#define BM 128
#define BN 128
#define STAGES 3
#define MAT_BYTES 16384
#define STAGE_BYTES (2 * MAT_BYTES)        // Ah, Bh = 32768
#define SMEM_GEMM (STAGES * STAGE_BYTES)   // 98304 -> 2 CTAs/SM

// GEMM modes
#define M_BIASRELU  1   // store + bias + relu
#define M_STATS     3   // plain store + fused column sum/sumsq partials (no bias)
#define M_PACK      4   // bias + relu + dual write (fp32 C and fp16 Cp)

// ---------------- scratch ----------------
__device__ float g_buf[(size_t)BATCH * CH_H];
__device__ float g_psum[SPLITS * CH_H];
__device__ float g_psq [SPLITS * CH_H];
__device__ float g_scale[CH_H];
__device__ float g_shift[CH_H];
__device__ __half g_Ah[(size_t)BATCH * DIM];
__device__ __half g_Ah2[(size_t)BATCH * CH_H];      // layer-3 packed output (no aliasing)
__device__ __half g_Bh[(size_t)DIM * CH_H];

// ---------------- helpers ----------------
__device__ __forceinline__ uint32_t smem_u32(const void* p) {
    uint32_t a;
    asm("{ .reg .u64 t; cvta.to.shared.u64 t, %1; cvt.u32.u64 %0, t; }" : "=r"(a) : "l"(p));
    return a;
}
__device__ __forceinline__ void cp16(uint32_t s, const void* g) {
    asm volatile("cp.async.cg.shared.global [%0], [%1], 16;" :: "r"(s), "l"(g));
}
#define CP_COMMIT() asm volatile("cp.async.commit_group;" ::: "memory")
#define CP_WAIT1()  asm volatile("cp.async.wait_group 1;" ::: "memory")

__device__ __forceinline__ void ldmx4(uint32_t* r, uint32_t addr) {
    asm volatile("ldmatrix.sync.aligned.m8n8.x4.shared.b16 {%0,%1,%2,%3}, [%4];"
                 : "=r"(r[0]), "=r"(r[1]), "=r"(r[2]), "=r"(r[3]) : "r"(addr));
}
__device__ __forceinline__ void mma16816(float* d, const uint32_t* a, const uint32_t* b) {
    asm volatile("mma.sync.aligned.m16n8k16.row.col.f32.f16.f16.f32 "
                 "{%0,%1,%2,%3}, {%4,%5,%6,%7}, {%8,%9}, {%0,%1,%2,%3};"
                 : "+f"(d[0]), "+f"(d[1]), "+f"(d[2]), "+f"(d[3])
                 : "r"(a[0]), "r"(a[1]), "r"(a[2]), "r"(a[3]), "r"(b[0]), "r"(b[1]));
}
__device__ __forceinline__ uint32_t pack2h(float f0, float f1) {
    __half h0 = __float2half_rn(f0);
    __half h1 = __float2half_rn(f1);
    return (uint32_t)__half_as_ushort(h0) | ((uint32_t)__half_as_ushort(h1) << 16);
}

// ---------------- score + reweight + pack A (layer-1 input) ----------------
__global__ __launch_bounds__(512) void score_pack(
    const float* __restrict__ ft0, const float* __restrict__ ft1,
    const float* __restrict__ ft2, const float* __restrict__ key,
    float* __restrict__ ft_all, __half* __restrict__ Ah)
{
    const int row = blockIdx.x, t = threadIdx.x;
    const int warp = t >> 5, lane = t & 31;
    __shared__ float wsum[16];
    __shared__ float sc[NCHUNK];
    const float kv = key[t];
    float x[NCHUNK];
#pragma unroll
    for (int c = 0; c < NCHUNK; ++c) {
        const float* src = (c < 4) ? ft0 : ((c < 8) ? ft1 : ft2);
        x[c] = src[(size_t)row * CH_H + (c & 3) * CHUNK + t];
    }
#pragma unroll
    for (int c = 0; c < NCHUNK; ++c) {
        float p = x[c] * kv;
#pragma unroll
        for (int o = 16; o; o >>= 1) p += __shfl_xor_sync(0xffffffffu, p, o);
        if (lane == 0) wsum[warp] = p;
        __syncthreads();
        if (warp == 0) {
            float q = (lane < 16) ? wsum[lane] : 0.f;
#pragma unroll
            for (int o = 8; o; o >>= 1) q += __shfl_xor_sync(0xffffffffu, q, o);
            if (lane == 0) sc[c] = q;
        }
        __syncthreads();
    }
    float mx = sc[0];
#pragma unroll
    for (int c = 1; c < NCHUNK; ++c) mx = fmaxf(mx, sc[c]);
    float e[NCHUNK], s = 0.f;
#pragma unroll
    for (int c = 0; c < NCHUNK; ++c) { e[c] = expf(sc[c] - mx); s += e[c]; }
    const float inv = 1.0f / s;
#pragma unroll
    for (int c = 0; c < NCHUNK; ++c) {
        float v = x[c] * (1.0f + e[c] * inv);
        size_t idx = (size_t)row * DIM + c * CHUNK + t;
        ft_all[idx] = v;
        Ah[idx] = __float2half_rn(v);
    }
}

// ---------------- BN apply + pack ----------------
__global__ __launch_bounds__(256) void bn_pack(
    const float* __restrict__ Y, __half* __restrict__ Ah, int K)
{
    size_t i = ((size_t)blockIdx.x * 256 + threadIdx.x) * 8;
    int col = (int)(i % K);
    float4 y0 = *(const float4*)(Y + i);
    float4 y1 = *(const float4*)(Y + i + 4);
    float4 s0 = *(const float4*)(g_scale + col);
    float4 s1 = *(const float4*)(g_scale + col + 4);
    float4 h0 = *(const float4*)(g_shift + col);
    float4 h1 = *(const float4*)(g_shift + col + 4);
    uint4 hp;
    hp.x = pack2h(fmaf(y0.x, s0.x, h0.x), fmaf(y0.y, s0.y, h0.y));
    hp.y = pack2h(fmaf(y0.z, s0.z, h0.z), fmaf(y0.w, s0.w, h0.w));
    hp.z = pack2h(fmaf(y1.x, s1.x, h1.x), fmaf(y1.y, s1.y, h1.y));
    hp.w = pack2h(fmaf(y1.z, s1.z, h1.z), fmaf(y1.w, s1.w, h1.w));
    *(uint4*)((char*)Ah + i * 2) = hp;
}

// ---------------- pack W: fp32 [K,N] -> fp16 [N,K] (transpose) ----------
__global__ __launch_bounds__(256) void pack_W_t(
    const float* __restrict__ W, __half* __restrict__ Bh, int K, int N)
{
    __shared__ float sm[32][33];
    const int k0 = blockIdx.x * 32, n0 = blockIdx.y * 32;
    const int tx = threadIdx.x & 31, ty = threadIdx.x >> 5;
#pragma unroll
    for (int i = 0; i < 4; ++i)
        sm[ty + 8 * i][tx] = W[(size_t)(k0 + ty + 8 * i) * N + n0 + tx];
    __syncthreads();
    const int kp = threadIdx.x & 15;
    const int nb = threadIdx.x >> 4;
#pragma unroll
    for (int j = 0; j < 2; ++j) {
        int n = nb + j * 16;
        *(uint32_t*)&Bh[(size_t)(n0 + n) * K + k0 + kp * 2] =
            pack2h(sm[kp * 2][n], sm[kp * 2 + 1][n]);
    }
}

// ---------------- mma.sync GEMM: fp16 single-pass, modal epilogue -------------
template <int MODE>
__global__ __launch_bounds__(256, 2) void gemm_mma(
    const __half* __restrict__ Ah, const __half* __restrict__ Bh,
    const float* __restrict__ bias, float* __restrict__ C,
    __half* __restrict__ Cp, int N, int K)
{
    extern __shared__ __align__(128) char smem[];
    const uint32_t sb = smem_u32(smem);
    const int tid = threadIdx.x, lane = tid & 31, wid = tid >> 5;
    const int wm = wid & 1, wn = wid >> 1;
    const int m0 = blockIdx.y * BM, n0 = blockIdx.x * BN;
    const int KT = K >> 6;

    const __half* g0 = Ah + (size_t)m0 * K;
    const __half* g1 = Bh + (size_t)n0 * K;

    float acc[4][4][4];
#pragma unroll
    for (int a = 0; a < 4; ++a)
#pragma unroll
        for (int b = 0; b < 4; ++b)
#pragma unroll
            for (int c = 0; c < 4; ++c) acc[a][b][c] = 0.f;

    auto load_stage = [&](int slot, int kt) {
        const uint32_t st = sb + slot * STAGE_BYTES;
        const int k0 = kt << 6;
        const __half* gs[2] = {g0, g1};
#pragma unroll
        for (int mtx = 0; mtx < 2; ++mtx) {
            const uint32_t base = st + mtx * MAT_BYTES;
            const __half* g = gs[mtx];
#pragma unroll
            for (int i = 0; i < 4; ++i) {
                int q = tid + i * 256;
                int row = q >> 3, c = q & 7;
                uint32_t sa = base + (((row << 3) + (c ^ (row & 7))) << 4);
                cp16(sa, g + (size_t)row * K + k0 + c * 8);
            }
        }
    };

    load_stage(0, 0); CP_COMMIT();
    load_stage(1, 1); CP_COMMIT();

    int slot = 0;
    for (int kt = 0; kt < KT; ++kt) {
        CP_WAIT1();
        __syncthreads();

        int nk = kt + 2;
        if (nk < KT) {
            int ns = slot + 2; if (ns >= STAGES) ns -= STAGES;
            load_stage(ns, nk);
            CP_COMMIT();
        }

        const uint32_t st = sb + slot * STAGE_BYTES;
#pragma unroll
        for (int kk = 0; kk < 4; ++kk) {
            const int cA = (kk << 1) + (lane >> 4);
            uint32_t bfr[4][2], afr[4][4];
#pragma unroll
            for (int half = 0; half < 2; ++half) {
                int row = wn * 32 + half * 16 + (lane & 15);
                uint32_t ad = st + MAT_BYTES + (((row << 3) + (cA ^ (row & 7))) << 4);
                uint32_t r[4];
                ldmx4(r, ad);
                bfr[half * 2][0] = r[0]; bfr[half * 2][1] = r[2];
                bfr[half * 2 + 1][0] = r[1]; bfr[half * 2 + 1][1] = r[3];
            }
#pragma unroll
            for (int mi = 0; mi < 4; ++mi) {
                int row = wm * 64 + mi * 16 + (lane & 15);
                ldmx4(afr[mi], st + (((row << 3) + (cA ^ (row & 7))) << 4));
            }
#pragma unroll
            for (int mi = 0; mi < 4; ++mi)
#pragma unroll
                for (int ni = 0; ni < 4; ++ni)
                    mma16816(acc[mi][ni], afr[mi], bfr[ni]);
        }

        if (++slot >= STAGES) slot = 0;
    }

    // ---------------- store epilogue ----------------
    const int gro = lane >> 2, t4 = lane & 3;
    const int colb = n0 + wn * 32 + t4 * 2;
#pragma unroll
    for (int mi = 0; mi < 4; ++mi) {
#pragma unroll
        for (int half = 0; half < 2; ++half) {
            int r = m0 + wm * 64 + mi * 16 + gro + half * 8;
            float* crow = C + (size_t)r * N;
#pragma unroll
            for (int ni = 0; ni < 4; ++ni) {
                int col = colb + ni * 8;
                float x = acc[mi][ni][half * 2 + 0];
                float y = acc[mi][ni][half * 2 + 1];
                if (MODE == M_BIASRELU || MODE == M_PACK) {
                    x += bias[col]; y += bias[col + 1];
                    x = fmaxf(x, 0.f); y = fmaxf(y, 0.f);
                }
                *(float2*)(crow + col) = make_float2(x, y);
                if (MODE == M_PACK) {
                    __half* prow = Cp + (size_t)r * N;
                    *(__half2*)(prow + col) = __floats2half2_rn(x, y);
                }
            }
        }
    }

    // ---------------- fused BN column-stats partials ----------------
    if (MODE == M_STATS) {
        float s[8], q[8];
#pragma unroll
        for (int ni = 0; ni < 4; ++ni)
#pragma unroll
            for (int j = 0; j < 2; ++j) {
                float ss = 0.f, qq = 0.f;
#pragma unroll
                for (int mi = 0; mi < 4; ++mi)
#pragma unroll
                    for (int half = 0; half < 2; ++half) {
                        float v = acc[mi][ni][half * 2 + j];
                        ss += v; qq = fmaf(v, v, qq);
                    }
                s[ni * 2 + j] = ss; q[ni * 2 + j] = qq;
            }
        // reduce over gro (lane bits 2..4)
#pragma unroll
        for (int m = 4; m <= 16; m <<= 1)
#pragma unroll
            for (int t = 0; t < 8; ++t) {
                s[t] += __shfl_xor_sync(0xffffffffu, s[t], m);
                q[t] += __shfl_xor_sync(0xffffffffu, q[t], m);
            }
        __syncthreads();                    // stage smem now reusable
        float* sm_s = (float*)smem;         // [2][128]
        float* sm_q = sm_s + 256;
        if (lane < 4) {                     // gro == 0, t4 == lane
#pragma unroll
            for (int ni = 0; ni < 4; ++ni)
#pragma unroll
                for (int j = 0; j < 2; ++j) {
                    int c = wn * 32 + lane * 2 + ni * 8 + j;
                    sm_s[wm * 128 + c] = s[ni * 2 + j];
                    sm_q[wm * 128 + c] = q[ni * 2 + j];
                }
        }
        __syncthreads();
        if (tid < 128) {
            g_psum[blockIdx.y * N + n0 + tid] = sm_s[tid] + sm_s[128 + tid];
            g_psq [blockIdx.y * N + n0 + tid] = sm_q[tid] + sm_q[128 + tid];
        }
    }
}

// ---------------- BN scale/shift from partials ----------------
__global__ __launch_bounds__(256) void colstats_final(
    const float* __restrict__ g, const float* __restrict__ beta, int N, float invM)
{
    const int c = blockIdx.x * blockDim.x + threadIdx.x;
    float s = 0.f, q = 0.f;
#pragma unroll 4
    for (int i = 0; i < SPLITS; ++i) { s += g_psum[i * N + c]; q += g_psq[i * N + c]; }
    float m = s * invM;
    float v = q * invM - m * m;
    float sc = g[c] * rsqrtf(v + EPSBN);
    g_scale[c] = sc;
    g_shift[c] = beta[c] - m * sc;
}

// ---------------- launch ----------------
extern "C" void kernel_launch(void* const* d_in, const int* in_sizes, int n_in,
                              void* d_out, int out_size)
{
    const float* ft0   = (const float*)d_in[1];
    const float* ft1   = (const float*)d_in[2];
    const float* ft2   = (const float*)d_in[3];
    const float* key   = (const float*)d_in[4];
    const float* W1    = (const float*)d_in[5];
    const float* g1    = (const float*)d_in[7];
    const float* beta1 = (const float*)d_in[8];
    const float* W2    = (const float*)d_in[9];
    const float* g2    = (const float*)d_in[11];
    const float* beta2 = (const float*)d_in[12];
    const float* W3    = (const float*)d_in[13];
    const float* b3    = (const float*)d_in[14];
    const float* We    = (const float*)d_in[15];
    const float* bE    = (const float*)d_in[16];

    float* out     = (float*)d_out;
    float* aligned = out;
    float* extend  = aligned + (size_t)BATCH * CH_H;
    float* ftall   = extend  + (size_t)BATCH * DIM;

    float* buf;
    __half *Ah, *Ah2, *Bh;
    cudaGetSymbolAddress((void**)&buf, g_buf);
    cudaGetSymbolAddress((void**)&Ah, g_Ah);
    cudaGetSymbolAddress((void**)&Ah2, g_Ah2);
    cudaGetSymbolAddress((void**)&Bh, g_Bh);

    cudaFuncSetAttribute(gemm_mma<M_BIASRELU>, cudaFuncAttributeMaxDynamicSharedMemorySize, SMEM_GEMM);
    cudaFuncSetAttribute(gemm_mma<M_STATS>,    cudaFuncAttributeMaxDynamicSharedMemorySize, SMEM_GEMM);
    cudaFuncSetAttribute(gemm_mma<M_PACK>,     cudaFuncAttributeMaxDynamicSharedMemorySize, SMEM_GEMM);

    const int MT = BATCH / BM;                    // 64
    const int PB = BATCH * CH_H / 8 / 256;        // pack blocks

    // 1) score + reweight + pack A1
    score_pack<<<BATCH, 512>>>(ft0, ft1, ft2, key, ftall, Ah);

    // 2) layer 1 (K=6144): fused stats epilogue; bias cancels in BN
    pack_W_t<<<dim3(DIM / 32, CH_H / 32), 256>>>(W1, Bh, DIM, CH_H);
    gemm_mma<M_STATS><<<dim3(CH_H / BN, MT), 256, SMEM_GEMM>>>(
        Ah, Bh, nullptr, buf, nullptr, CH_H, DIM);
    colstats_final<<<CH_H / 256, 256>>>(g1, beta1, CH_H, 1.0f / BATCH);
    bn_pack<<<PB, 256>>>(buf, Ah, CH_H);

    // 3) layer 2 (K=2048): fused stats epilogue; bias cancels in BN
    pack_W_t<<<dim3(CH_H / 32, CH_H / 32), 256>>>(W2, Bh, CH_H, CH_H);
    gemm_mma<M_STATS><<<dim3(CH_H / BN, MT), 256, SMEM_GEMM>>>(
        Ah, Bh, nullptr, buf, nullptr, CH_H, CH_H);
    colstats_final<<<CH_H / 256, 256>>>(g2, beta2, CH_H, 1.0f / BATCH);
    bn_pack<<<PB, 256>>>(buf, Ah, CH_H);

    // 4) layer 3: bias+relu epilogue, dual write fp32 'aligned' + fp16 Ah2
    pack_W_t<<<dim3(CH_H / 32, CH_H / 32), 256>>>(W3, Bh, CH_H, CH_H);
    gemm_mma<M_PACK><<<dim3(CH_H / BN, MT), 256, SMEM_GEMM>>>(
        Ah, Bh, b3, aligned, Ah2, CH_H, CH_H);

    // 5) extend = relu(aligned @ We + bE), input = Ah2
    pack_W_t<<<dim3(CH_H / 32, DIM / 32), 256>>>(We, Bh, CH_H, DIM);
    gemm_mma<M_BIASRELU><<<dim3(DIM / BN, MT), 256, SMEM_GEMM>>>(
        Ah2, Bh, bE, extend, nullptr, DIM, CH_H);
}

// round 13
// speedup vs baseline: 1.0452x; 1.0154x over previous
#include <cuda_runtime.h>
#include <cuda_fp16.h>
#include <cstdint>

// Problem dims
#define BATCH   8192
#define CH_H    2048
#define DIM     6144
#define CHUNK   512
#define NCHUNK  12
#define EPSBN   1e-5f
#define SPLITS  64

// GEMM tiling (128x128 tile, 3-stage, 2 CTAs/SM, single-pass fp16)
#define BM 128
#define BN 128
#define STAGES 3
#define MAT_BYTES 16384
#define STAGE_BYTES (2 * MAT_BYTES)        // Ah, Bh = 32768
#define SMEM_GEMM (STAGES * STAGE_BYTES)   // 98304 -> 2 CTAs/SM

// GEMM modes
#define M_BIASRELU   1   // bias + relu, fp32 store
#define M_PACK       4   // bias + relu, fp32 store + fp16 store
#define M_STATSPACK  5   // no bias, fp16 store only, fused column stats partials

// ---------------- scratch ----------------
__device__ float g_psum[SPLITS * CH_H];
__device__ float g_psq [SPLITS * CH_H];
__device__ float g_scale[CH_H];
__device__ float g_shift[CH_H];
__device__ float g_bias[CH_H];
__device__ __half g_Ah[(size_t)BATCH * DIM];
__device__ __half g_Ah2[(size_t)BATCH * CH_H];
__device__ __half g_Bh[(size_t)DIM * CH_H];

// ---------------- helpers ----------------
__device__ __forceinline__ uint32_t smem_u32(const void* p) {
    uint32_t a;
    asm("{ .reg .u64 t; cvta.to.shared.u64 t, %1; cvt.u32.u64 %0, t; }" : "=r"(a) : "l"(p));
    return a;
}
__device__ __forceinline__ void cp16(uint32_t s, const void* g) {
    asm volatile("cp.async.cg.shared.global [%0], [%1], 16;" :: "r"(s), "l"(g));
}
#define CP_COMMIT() asm volatile("cp.async.commit_group;" ::: "memory")
#define CP_WAIT1()  asm volatile("cp.async.wait_group 1;" ::: "memory")

__device__ __forceinline__ void ldmx4(uint32_t* r, uint32_t addr) {
    asm volatile("ldmatrix.sync.aligned.m8n8.x4.shared.b16 {%0,%1,%2,%3}, [%4];"
                 : "=r"(r[0]), "=r"(r[1]), "=r"(r[2]), "=r"(r[3]) : "r"(addr));
}
__device__ __forceinline__ void mma16816(float* d, const uint32_t* a, const uint32_t* b) {
    asm volatile("mma.sync.aligned.m16n8k16.row.col.f32.f16.f16.f32 "
                 "{%0,%1,%2,%3}, {%4,%5,%6,%7}, {%8,%9}, {%0,%1,%2,%3};"
                 : "+f"(d[0]), "+f"(d[1]), "+f"(d[2]), "+f"(d[3])
                 : "r"(a[0]), "r"(a[1]), "r"(a[2]), "r"(a[3]), "r"(b[0]), "r"(b[1]));
}
__device__ __forceinline__ uint32_t pack2h(float f0, float f1) {
    __half h0 = __float2half_rn(f0);
    __half h1 = __float2half_rn(f1);
    return (uint32_t)__half_as_ushort(h0) | ((uint32_t)__half_as_ushort(h1) << 16);
}

// ---------------- score + reweight + pack A (layer-1 input) ----------------
__global__ __launch_bounds__(512) void score_pack(
    const float* __restrict__ ft0, const float* __restrict__ ft1,
    const float* __restrict__ ft2, const float* __restrict__ key,
    float* __restrict__ ft_all, __half* __restrict__ Ah)
{
    const int row = blockIdx.x, t = threadIdx.x;
    const int warp = t >> 5, lane = t & 31;
    __shared__ float wsum[16];
    __shared__ float sc[NCHUNK];
    const float kv = key[t];
    float x[NCHUNK];
#pragma unroll
    for (int c = 0; c < NCHUNK; ++c) {
        const float* src = (c < 4) ? ft0 : ((c < 8) ? ft1 : ft2);
        x[c] = src[(size_t)row * CH_H + (c & 3) * CHUNK + t];
    }
#pragma unroll
    for (int c = 0; c < NCHUNK; ++c) {
        float p = x[c] * kv;
#pragma unroll
        for (int o = 16; o; o >>= 1) p += __shfl_xor_sync(0xffffffffu, p, o);
        if (lane == 0) wsum[warp] = p;
        __syncthreads();
        if (warp == 0) {
            float q = (lane < 16) ? wsum[lane] : 0.f;
#pragma unroll
            for (int o = 8; o; o >>= 1) q += __shfl_xor_sync(0xffffffffu, q, o);
            if (lane == 0) sc[c] = q;
        }
        __syncthreads();
    }
    float mx = sc[0];
#pragma unroll
    for (int c = 1; c < NCHUNK; ++c) mx = fmaxf(mx, sc[c]);
    float e[NCHUNK], s = 0.f;
#pragma unroll
    for (int c = 0; c < NCHUNK; ++c) { e[c] = expf(sc[c] - mx); s += e[c]; }
    const float inv = 1.0f / s;
#pragma unroll
    for (int c = 0; c < NCHUNK; ++c) {
        float v = x[c] * (1.0f + e[c] * inv);
        size_t idx = (size_t)row * DIM + c * CHUNK + t;
        ft_all[idx] = v;
        Ah[idx] = __float2half_rn(v);
    }
}

// ---------------- pack W: fp32 [K,N] -> fp16 [N,K], optional row scale --------
__global__ __launch_bounds__(256) void pack_W_t(
    const float* __restrict__ W, __half* __restrict__ Bh, int K, int N,
    const float* __restrict__ rscale)
{
    __shared__ float sm[32][33];
    const int k0 = blockIdx.x * 32, n0 = blockIdx.y * 32;
    const int tx = threadIdx.x & 31, ty = threadIdx.x >> 5;
#pragma unroll
    for (int i = 0; i < 4; ++i)
        sm[ty + 8 * i][tx] = W[(size_t)(k0 + ty + 8 * i) * N + n0 + tx];
    __syncthreads();
    const int kp = threadIdx.x & 15;
    const int nb = threadIdx.x >> 4;
    float sa = 1.f, sb = 1.f;
    if (rscale) { sa = rscale[k0 + kp * 2]; sb = rscale[k0 + kp * 2 + 1]; }
#pragma unroll
    for (int j = 0; j < 2; ++j) {
        int n = nb + j * 16;
        *(uint32_t*)&Bh[(size_t)(n0 + n) * K + k0 + kp * 2] =
            pack2h(sm[kp * 2][n] * sa, sm[kp * 2 + 1][n] * sb);
    }
}

// ---------------- mma.sync GEMM: fp16 single-pass, modal epilogue -------------
template <int MODE>
__global__ __launch_bounds__(256, 2) void gemm_mma(
    const __half* __restrict__ Ah, const __half* __restrict__ Bh,
    const float* __restrict__ bias, float* __restrict__ C,
    __half* __restrict__ Cp, int N, int K)
{
    extern __shared__ __align__(128) char smem[];
    const uint32_t sb = smem_u32(smem);
    const int tid = threadIdx.x, lane = tid & 31, wid = tid >> 5;
    const int wm = wid & 1, wn = wid >> 1;
    const int m0 = blockIdx.y * BM, n0 = blockIdx.x * BN;
    const int KT = K >> 6;

    const __half* g0 = Ah + (size_t)m0 * K;
    const __half* g1 = Bh + (size_t)n0 * K;

    float acc[4][4][4];
#pragma unroll
    for (int a = 0; a < 4; ++a)
#pragma unroll
        for (int b = 0; b < 4; ++b)
#pragma unroll
            for (int c = 0; c < 4; ++c) acc[a][b][c] = 0.f;

    auto load_stage = [&](int slot, int kt) {
        const uint32_t st = sb + slot * STAGE_BYTES;
        const int k0 = kt << 6;
        const __half* gs[2] = {g0, g1};
#pragma unroll
        for (int mtx = 0; mtx < 2; ++mtx) {
            const uint32_t base = st + mtx * MAT_BYTES;
            const __half* g = gs[mtx];
#pragma unroll
            for (int i = 0; i < 4; ++i) {
                int q = tid + i * 256;
                int row = q >> 3, c = q & 7;
                uint32_t sa = base + (((row << 3) + (c ^ (row & 7))) << 4);
                cp16(sa, g + (size_t)row * K + k0 + c * 8);
            }
        }
    };

    load_stage(0, 0); CP_COMMIT();
    load_stage(1, 1); CP_COMMIT();

    int slot = 0;
    for (int kt = 0; kt < KT; ++kt) {
        CP_WAIT1();
        __syncthreads();

        int nk = kt + 2;
        if (nk < KT) {
            int ns = slot + 2; if (ns >= STAGES) ns -= STAGES;
            load_stage(ns, nk);
            CP_COMMIT();
        }

        const uint32_t st = sb + slot * STAGE_BYTES;
#pragma unroll
        for (int kk = 0; kk < 4; ++kk) {
            const int cA = (kk << 1) + (lane >> 4);
            uint32_t bfr[4][2], afr[4][4];
#pragma unroll
            for (int half = 0; half < 2; ++half) {
                int row = wn * 32 + half * 16 + (lane & 15);
                uint32_t ad = st + MAT_BYTES + (((row << 3) + (cA ^ (row & 7))) << 4);
                uint32_t r[4];
                ldmx4(r, ad);
                bfr[half * 2][0] = r[0]; bfr[half * 2][1] = r[2];
                bfr[half * 2 + 1][0] = r[1]; bfr[half * 2 + 1][1] = r[3];
            }
#pragma unroll
            for (int mi = 0; mi < 4; ++mi) {
                int row = wm * 64 + mi * 16 + (lane & 15);
                ldmx4(afr[mi], st + (((row << 3) + (cA ^ (row & 7))) << 4));
            }
#pragma unroll
            for (int mi = 0; mi < 4; ++mi)
#pragma unroll
                for (int ni = 0; ni < 4; ++ni)
                    mma16816(acc[mi][ni], afr[mi], bfr[ni]);
        }

        if (++slot >= STAGES) slot = 0;
    }

    // ---------------- store epilogue ----------------
    const int gro = lane >> 2, t4 = lane & 3;
    const int colb = n0 + wn * 32 + t4 * 2;
#pragma unroll
    for (int mi = 0; mi < 4; ++mi) {
#pragma unroll
        for (int half = 0; half < 2; ++half) {
            int r = m0 + wm * 64 + mi * 16 + gro + half * 8;
#pragma unroll
            for (int ni = 0; ni < 4; ++ni) {
                int col = colb + ni * 8;
                float x = acc[mi][ni][half * 2 + 0];
                float y = acc[mi][ni][half * 2 + 1];
                if (MODE == M_BIASRELU || MODE == M_PACK) {
                    x += bias[col]; y += bias[col + 1];
                    x = fmaxf(x, 0.f); y = fmaxf(y, 0.f);
                }
                if (MODE == M_BIASRELU || MODE == M_PACK) {
                    float* crow = C + (size_t)r * N;
                    *(float2*)(crow + col) = make_float2(x, y);
                }
                if (MODE == M_PACK || MODE == M_STATSPACK) {
                    __half* prow = Cp + (size_t)r * N;
                    *(__half2*)(prow + col) = __floats2half2_rn(x, y);
                }
            }
        }
    }

    // ---------------- fused BN column-stats partials ----------------
    if (MODE == M_STATSPACK) {
        float s[8], q[8];
#pragma unroll
        for (int ni = 0; ni < 4; ++ni)
#pragma unroll
            for (int j = 0; j < 2; ++j) {
                float ss = 0.f, qq = 0.f;
#pragma unroll
                for (int mi = 0; mi < 4; ++mi)
#pragma unroll
                    for (int half = 0; half < 2; ++half) {
                        float v = acc[mi][ni][half * 2 + j];
                        ss += v; qq = fmaf(v, v, qq);
                    }
                s[ni * 2 + j] = ss; q[ni * 2 + j] = qq;
            }
#pragma unroll
        for (int m = 4; m <= 16; m <<= 1)
#pragma unroll
            for (int t = 0; t < 8; ++t) {
                s[t] += __shfl_xor_sync(0xffffffffu, s[t], m);
                q[t] += __shfl_xor_sync(0xffffffffu, q[t], m);
            }
        __syncthreads();
        float* sm_s = (float*)smem;         // [2][128]
        float* sm_q = sm_s + 256;
        if (lane < 4) {
#pragma unroll
            for (int ni = 0; ni < 4; ++ni)
#pragma unroll
                for (int j = 0; j < 2; ++j) {
                    int c = wn * 32 + lane * 2 + ni * 8 + j;
                    sm_s[wm * 128 + c] = s[ni * 2 + j];
                    sm_q[wm * 128 + c] = q[ni * 2 + j];
                }
        }
        __syncthreads();
        if (tid < 128) {
            g_psum[blockIdx.y * N + n0 + tid] = sm_s[tid] + sm_s[128 + tid];
            g_psq [blockIdx.y * N + n0 + tid] = sm_q[tid] + sm_q[128 + tid];
        }
    }
}

// ---------------- BN scale/shift from partials (split-parallel) ----------------
__global__ __launch_bounds__(256) void colstats_final(
    const float* __restrict__ g, const float* __restrict__ beta, int N, float invM)
{
    __shared__ float ss[8][32], sq[8][32];
    const int cl = threadIdx.x & 31, grp = threadIdx.x >> 5;   // 8 split-groups
    const int c = blockIdx.x * 32 + cl;
    float s = 0.f, q = 0.f;
#pragma unroll
    for (int i = 0; i < 8; ++i) {
        int sp = grp * 8 + i;
        s += g_psum[sp * N + c];
        q += g_psq [sp * N + c];
    }
    ss[grp][cl] = s; sq[grp][cl] = q;
    __syncthreads();
    if (grp == 0) {
#pragma unroll
        for (int i = 1; i < 8; ++i) { s += ss[i][cl]; q += sq[i][cl]; }
        float m = s * invM;
        float v = q * invM - m * m;
        float sc = g[c] * rsqrtf(v + EPSBN);
        g_scale[c] = sc;
        g_shift[c] = beta[c] - m * sc;
    }
}

// ---------------- bias3' = shift @ W3 partials, then + b3 ----------------
__global__ __launch_bounds__(256) void bias_mv(const float* __restrict__ W, int N)
{
    const int n = blockIdx.x * 256 + threadIdx.x;
    const int k0 = blockIdx.y * 128;
    float s = 0.f;
#pragma unroll 4
    for (int k = k0; k < k0 + 128; ++k)
        s = fmaf(g_shift[k], W[(size_t)k * N + n], s);
    g_psum[blockIdx.y * N + n] = s;
}
__global__ __launch_bounds__(256) void bias_fin(const float* __restrict__ b, int N)
{
    const int n = blockIdx.x * 256 + threadIdx.x;
    float s = b[n];
#pragma unroll
    for (int i = 0; i < 16; ++i) s += g_psum[i * N + n];
    g_bias[n] = s;
}

// ---------------- launch ----------------
extern "C" void kernel_launch(void* const* d_in, const int* in_sizes, int n_in,
                              void* d_out, int out_size)
{
    const float* ft0   = (const float*)d_in[1];
    const float* ft1   = (const float*)d_in[2];
    const float* ft2   = (const float*)d_in[3];
    const float* key   = (const float*)d_in[4];
    const float* W1    = (const float*)d_in[5];
    const float* g1    = (const float*)d_in[7];
    const float* beta1 = (const float*)d_in[8];
    const float* W2    = (const float*)d_in[9];
    const float* g2    = (const float*)d_in[11];
    const float* beta2 = (const float*)d_in[12];
    const float* W3    = (const float*)d_in[13];
    const float* b3    = (const float*)d_in[14];
    const float* We    = (const float*)d_in[15];
    const float* bE    = (const float*)d_in[16];

    float* out     = (float*)d_out;
    float* aligned = out;
    float* extend  = aligned + (size_t)BATCH * CH_H;
    float* ftall   = extend  + (size_t)BATCH * DIM;

    __half *Ah, *Ah2, *Bh;
    float *scaleP, *biasP;
    cudaGetSymbolAddress((void**)&Ah, g_Ah);
    cudaGetSymbolAddress((void**)&Ah2, g_Ah2);
    cudaGetSymbolAddress((void**)&Bh, g_Bh);
    cudaGetSymbolAddress((void**)&scaleP, g_scale);
    cudaGetSymbolAddress((void**)&biasP, g_bias);

    cudaFuncSetAttribute(gemm_mma<M_BIASRELU>,  cudaFuncAttributeMaxDynamicSharedMemorySize, SMEM_GEMM);
    cudaFuncSetAttribute(gemm_mma<M_PACK>,      cudaFuncAttributeMaxDynamicSharedMemorySize, SMEM_GEMM);
    cudaFuncSetAttribute(gemm_mma<M_STATSPACK>, cudaFuncAttributeMaxDynamicSharedMemorySize, SMEM_GEMM);

    const int MT = BATCH / BM;  // 64

    // 1) score + reweight + pack A1 (fp16) ; ft_all output
    score_pack<<<BATCH, 512>>>(ft0, ft1, ft2, key, ftall, Ah);

    // 2) layer 1 (K=6144): raw y1 -> fp16 Ah2 + fused stats (bias cancels in BN1,
    //    BN1 shift contribution cancels in BN2)
    pack_W_t<<<dim3(DIM / 32, CH_H / 32), 256>>>(W1, Bh, DIM, CH_H, nullptr);
    gemm_mma<M_STATSPACK><<<dim3(CH_H / BN, MT), 256, SMEM_GEMM>>>(
        Ah, Bh, nullptr, nullptr, Ah2, CH_H, DIM);
    colstats_final<<<CH_H / 32, 256>>>(g1, beta1, CH_H, 1.0f / BATCH);

    // 3) layer 2 (K=2048): W2 scaled by s1 rows; raw y2 -> fp16 Ah + fused stats
    pack_W_t<<<dim3(CH_H / 32, CH_H / 32), 256>>>(W2, Bh, CH_H, CH_H, scaleP);
    gemm_mma<M_STATSPACK><<<dim3(CH_H / BN, MT), 256, SMEM_GEMM>>>(
        Ah2, Bh, nullptr, nullptr, Ah, CH_H, CH_H);
    colstats_final<<<CH_H / 32, 256>>>(g2, beta2, CH_H, 1.0f / BATCH);

    // 4) layer 3: W3 scaled by s2 rows; bias3' = t2 @ W3 + b3; relu; dual write
    pack_W_t<<<dim3(CH_H / 32, CH_H / 32), 256>>>(W3, Bh, CH_H, CH_H, scaleP);
    bias_mv<<<dim3(CH_H / 256, 16), 256>>>(W3, CH_H);
    bias_fin<<<CH_H / 256, 256>>>(b3, CH_H);
    gemm_mma<M_PACK><<<dim3(CH_H / BN, MT), 256, SMEM_GEMM>>>(
        Ah, Bh, biasP, aligned, Ah2, CH_H, CH_H);

    // 5) extend = relu(aligned @ We + bE), input = Ah2
    pack_W_t<<<dim3(CH_H / 32, DIM / 32), 256>>>(We, Bh, CH_H, DIM, nullptr);
    gemm_mma<M_BIASRELU><<<dim3(DIM / BN, MT), 256, SMEM_GEMM>>>(
        Ah2, Bh, bE, extend, nullptr, DIM, CH_H);
}

// round 14
// speedup vs baseline: 1.0595x; 1.0137x over previous
#include <cuda_runtime.h>
#include <cuda_fp16.h>
#include <cstdint>

// Problem dims
#define BATCH   8192
#define CH_H    2048
#define DIM     6144
#define CHUNK   512
#define NCHUNK  12
#define EPSBN   1e-5f
#define SPLITS  64

// GEMM tiling (128x128 tile, 3-stage, 2 CTAs/SM, single-pass fp16)
#define BM 128
#define BN 128
#define STAGES 3
#define MAT_BYTES 16384
#define STAGE_BYTES (2 * MAT_BYTES)        // Ah, Bh = 32768
#define SMEM_GEMM (STAGES * STAGE_BYTES)   // 98304 -> 2 CTAs/SM

// GEMM modes
#define M_BIASRELU   1   // bias + relu, fp32 store
#define M_PACK       4   // bias + relu, fp32 store + fp16 store
#define M_STATSPACK  5   // no bias, fp16 store only, fused column stats partials

// ---------------- scratch ----------------
__device__ float g_psum[SPLITS * CH_H];
__device__ float g_psq [SPLITS * CH_H];
__device__ float g_scale[CH_H];
__device__ float g_shift[CH_H];
__device__ float g_bias[CH_H];
__device__ __half g_Ah[(size_t)BATCH * DIM];
__device__ __half g_Ah2[(size_t)BATCH * CH_H];
__device__ __half g_Bh[(size_t)DIM * CH_H];

// ---------------- helpers ----------------
__device__ __forceinline__ uint32_t smem_u32(const void* p) {
    uint32_t a;
    asm("{ .reg .u64 t; cvta.to.shared.u64 t, %1; cvt.u32.u64 %0, t; }" : "=r"(a) : "l"(p));
    return a;
}
__device__ __forceinline__ void cp16(uint32_t s, const void* g) {
    asm volatile("cp.async.cg.shared.global [%0], [%1], 16;" :: "r"(s), "l"(g));
}
#define CP_COMMIT() asm volatile("cp.async.commit_group;" ::: "memory")
#define CP_WAIT1()  asm volatile("cp.async.wait_group 1;" ::: "memory")

__device__ __forceinline__ void ldmx4(uint32_t* r, uint32_t addr) {
    asm volatile("ldmatrix.sync.aligned.m8n8.x4.shared.b16 {%0,%1,%2,%3}, [%4];"
                 : "=r"(r[0]), "=r"(r[1]), "=r"(r[2]), "=r"(r[3]) : "r"(addr));
}
__device__ __forceinline__ void mma16816(float* d, const uint32_t* a, const uint32_t* b) {
    asm volatile("mma.sync.aligned.m16n8k16.row.col.f32.f16.f16.f32 "
                 "{%0,%1,%2,%3}, {%4,%5,%6,%7}, {%8,%9}, {%0,%1,%2,%3};"
                 : "+f"(d[0]), "+f"(d[1]), "+f"(d[2]), "+f"(d[3])
                 : "r"(a[0]), "r"(a[1]), "r"(a[2]), "r"(a[3]), "r"(b[0]), "r"(b[1]));
}
__device__ __forceinline__ uint32_t pack2h(float f0, float f1) {
    __half h0 = __float2half_rn(f0);
    __half h1 = __float2half_rn(f1);
    return (uint32_t)__half_as_ushort(h0) | ((uint32_t)__half_as_ushort(h1) << 16);
}

// ---------------- score + reweight + pack A (2-barrier version) ----------------
__global__ __launch_bounds__(512) void score_pack(
    const float* __restrict__ ft0, const float* __restrict__ ft1,
    const float* __restrict__ ft2, const float* __restrict__ key,
    float* __restrict__ ft_all, __half* __restrict__ Ah)
{
    const int row = blockIdx.x, t = threadIdx.x;
    const int warp = t >> 5, lane = t & 31;
    __shared__ float wsum[NCHUNK][16];
    __shared__ float sc[NCHUNK];
    const float kv = key[t];
    float x[NCHUNK];
#pragma unroll
    for (int c = 0; c < NCHUNK; ++c) {
        const float* src = (c < 4) ? ft0 : ((c < 8) ? ft1 : ft2);
        x[c] = src[(size_t)row * CH_H + (c & 3) * CHUNK + t];
    }
    // phase 1: per-warp reduction of all 12 chunk dots (no barriers)
#pragma unroll
    for (int c = 0; c < NCHUNK; ++c) {
        float p = x[c] * kv;
#pragma unroll
        for (int o = 16; o; o >>= 1) p += __shfl_xor_sync(0xffffffffu, p, o);
        if (lane == 0) wsum[c][warp] = p;
    }
    __syncthreads();
    // phase 2: warps 0..11 each finish one chunk (16 partials)
    if (warp < NCHUNK) {
        float q = (lane < 16) ? wsum[warp][lane] : 0.f;
#pragma unroll
        for (int o = 8; o; o >>= 1) q += __shfl_xor_sync(0xffffffffu, q, o);
        if (lane == 0) sc[warp] = q;
    }
    __syncthreads();
    // phase 3: softmax + reweight + dual write
    float mx = sc[0];
#pragma unroll
    for (int c = 1; c < NCHUNK; ++c) mx = fmaxf(mx, sc[c]);
    float e[NCHUNK], s = 0.f;
#pragma unroll
    for (int c = 0; c < NCHUNK; ++c) { e[c] = expf(sc[c] - mx); s += e[c]; }
    const float inv = 1.0f / s;
#pragma unroll
    for (int c = 0; c < NCHUNK; ++c) {
        float v = x[c] * (1.0f + e[c] * inv);
        size_t idx = (size_t)row * DIM + c * CHUNK + t;
        ft_all[idx] = v;
        Ah[idx] = __float2half_rn(v);
    }
}

// ---------------- pack W: fp32 [K,N] -> fp16 [N,K], optional row scale --------
__global__ __launch_bounds__(256) void pack_W_t(
    const float* __restrict__ W, __half* __restrict__ Bh, int K, int N,
    const float* __restrict__ rscale)
{
    __shared__ float sm[32][33];
    const int k0 = blockIdx.x * 32, n0 = blockIdx.y * 32;
    const int tx = threadIdx.x & 31, ty = threadIdx.x >> 5;
#pragma unroll
    for (int i = 0; i < 4; ++i)
        sm[ty + 8 * i][tx] = W[(size_t)(k0 + ty + 8 * i) * N + n0 + tx];
    __syncthreads();
    const int kp = threadIdx.x & 15;
    const int nb = threadIdx.x >> 4;
    float sa = 1.f, sb = 1.f;
    if (rscale) { sa = rscale[k0 + kp * 2]; sb = rscale[k0 + kp * 2 + 1]; }
#pragma unroll
    for (int j = 0; j < 2; ++j) {
        int n = nb + j * 16;
        *(uint32_t*)&Bh[(size_t)(n0 + n) * K + k0 + kp * 2] =
            pack2h(sm[kp * 2][n] * sa, sm[kp * 2 + 1][n] * sb);
    }
}

// ---------------- mma.sync GEMM: fp16 single-pass, modal epilogue -------------
template <int MODE>
__global__ __launch_bounds__(256, 2) void gemm_mma(
    const __half* __restrict__ Ah, const __half* __restrict__ Bh,
    const float* __restrict__ bias, float* __restrict__ C,
    __half* __restrict__ Cp, int N, int K)
{
    extern __shared__ __align__(128) char smem[];
    const uint32_t sb = smem_u32(smem);
    const int tid = threadIdx.x, lane = tid & 31, wid = tid >> 5;
    const int wm = wid & 1, wn = wid >> 1;
    const int m0 = blockIdx.y * BM, n0 = blockIdx.x * BN;
    const int KT = K >> 6;

    const __half* g0 = Ah + (size_t)m0 * K;
    const __half* g1 = Bh + (size_t)n0 * K;

    float acc[4][4][4];
#pragma unroll
    for (int a = 0; a < 4; ++a)
#pragma unroll
        for (int b = 0; b < 4; ++b)
#pragma unroll
            for (int c = 0; c < 4; ++c) acc[a][b][c] = 0.f;

    auto load_stage = [&](int slot, int kt) {
        const uint32_t st = sb + slot * STAGE_BYTES;
        const int k0 = kt << 6;
        const __half* gs[2] = {g0, g1};
#pragma unroll
        for (int mtx = 0; mtx < 2; ++mtx) {
            const uint32_t base = st + mtx * MAT_BYTES;
            const __half* g = gs[mtx];
#pragma unroll
            for (int i = 0; i < 4; ++i) {
                int q = tid + i * 256;
                int row = q >> 3, c = q & 7;
                uint32_t sa = base + (((row << 3) + (c ^ (row & 7))) << 4);
                cp16(sa, g + (size_t)row * K + k0 + c * 8);
            }
        }
    };

    load_stage(0, 0); CP_COMMIT();
    load_stage(1, 1); CP_COMMIT();

    int slot = 0;
    for (int kt = 0; kt < KT; ++kt) {
        CP_WAIT1();
        __syncthreads();

        int nk = kt + 2;
        if (nk < KT) {
            int ns = slot + 2; if (ns >= STAGES) ns -= STAGES;
            load_stage(ns, nk);
            CP_COMMIT();
        }

        const uint32_t st = sb + slot * STAGE_BYTES;
#pragma unroll
        for (int kk = 0; kk < 4; ++kk) {
            const int cA = (kk << 1) + (lane >> 4);
            uint32_t bfr[4][2], afr[4][4];
#pragma unroll
            for (int half = 0; half < 2; ++half) {
                int row = wn * 32 + half * 16 + (lane & 15);
                uint32_t ad = st + MAT_BYTES + (((row << 3) + (cA ^ (row & 7))) << 4);
                uint32_t r[4];
                ldmx4(r, ad);
                bfr[half * 2][0] = r[0]; bfr[half * 2][1] = r[2];
                bfr[half * 2 + 1][0] = r[1]; bfr[half * 2 + 1][1] = r[3];
            }
#pragma unroll
            for (int mi = 0; mi < 4; ++mi) {
                int row = wm * 64 + mi * 16 + (lane & 15);
                ldmx4(afr[mi], st + (((row << 3) + (cA ^ (row & 7))) << 4));
            }
#pragma unroll
            for (int mi = 0; mi < 4; ++mi)
#pragma unroll
                for (int ni = 0; ni < 4; ++ni)
                    mma16816(acc[mi][ni], afr[mi], bfr[ni]);
        }

        if (++slot >= STAGES) slot = 0;
    }

    // ---------------- store epilogue ----------------
    const int gro = lane >> 2, t4 = lane & 3;
    const int colb = n0 + wn * 32 + t4 * 2;
#pragma unroll
    for (int mi = 0; mi < 4; ++mi) {
#pragma unroll
        for (int half = 0; half < 2; ++half) {
            int r = m0 + wm * 64 + mi * 16 + gro + half * 8;
#pragma unroll
            for (int ni = 0; ni < 4; ++ni) {
                int col = colb + ni * 8;
                float x = acc[mi][ni][half * 2 + 0];
                float y = acc[mi][ni][half * 2 + 1];
                if (MODE == M_BIASRELU || MODE == M_PACK) {
                    x += bias[col]; y += bias[col + 1];
                    x = fmaxf(x, 0.f); y = fmaxf(y, 0.f);
                }
                if (MODE == M_BIASRELU || MODE == M_PACK) {
                    float* crow = C + (size_t)r * N;
                    *(float2*)(crow + col) = make_float2(x, y);
                }
                if (MODE == M_PACK || MODE == M_STATSPACK) {
                    __half* prow = Cp + (size_t)r * N;
                    *(__half2*)(prow + col) = __floats2half2_rn(x, y);
                }
            }
        }
    }

    // ---------------- fused BN column-stats partials ----------------
    if (MODE == M_STATSPACK) {
        float s[8], q[8];
#pragma unroll
        for (int ni = 0; ni < 4; ++ni)
#pragma unroll
            for (int j = 0; j < 2; ++j) {
                float ss = 0.f, qq = 0.f;
#pragma unroll
                for (int mi = 0; mi < 4; ++mi)
#pragma unroll
                    for (int half = 0; half < 2; ++half) {
                        float v = acc[mi][ni][half * 2 + j];
                        ss += v; qq = fmaf(v, v, qq);
                    }
                s[ni * 2 + j] = ss; q[ni * 2 + j] = qq;
            }
#pragma unroll
        for (int m = 4; m <= 16; m <<= 1)
#pragma unroll
            for (int t = 0; t < 8; ++t) {
                s[t] += __shfl_xor_sync(0xffffffffu, s[t], m);
                q[t] += __shfl_xor_sync(0xffffffffu, q[t], m);
            }
        __syncthreads();
        float* sm_s = (float*)smem;         // [2][128]
        float* sm_q = sm_s + 256;
        if (lane < 4) {
#pragma unroll
            for (int ni = 0; ni < 4; ++ni)
#pragma unroll
                for (int j = 0; j < 2; ++j) {
                    int c = wn * 32 + lane * 2 + ni * 8 + j;
                    sm_s[wm * 128 + c] = s[ni * 2 + j];
                    sm_q[wm * 128 + c] = q[ni * 2 + j];
                }
        }
        __syncthreads();
        if (tid < 128) {
            g_psum[blockIdx.y * N + n0 + tid] = sm_s[tid] + sm_s[128 + tid];
            g_psq [blockIdx.y * N + n0 + tid] = sm_q[tid] + sm_q[128 + tid];
        }
    }
}

// ---------------- BN scale/shift from partials (split-parallel) ----------------
__global__ __launch_bounds__(256) void colstats_final(
    const float* __restrict__ g, const float* __restrict__ beta, int N, float invM)
{
    __shared__ float ss[8][32], sq[8][32];
    const int cl = threadIdx.x & 31, grp = threadIdx.x >> 5;
    const int c = blockIdx.x * 32 + cl;
    float s = 0.f, q = 0.f;
#pragma unroll
    for (int i = 0; i < 8; ++i) {
        int sp = grp * 8 + i;
        s += g_psum[sp * N + c];
        q += g_psq [sp * N + c];
    }
    ss[grp][cl] = s; sq[grp][cl] = q;
    __syncthreads();
    if (grp == 0) {
#pragma unroll
        for (int i = 1; i < 8; ++i) { s += ss[i][cl]; q += sq[i][cl]; }
        float m = s * invM;
        float v = q * invM - m * m;
        float sc = g[c] * rsqrtf(v + EPSBN);
        g_scale[c] = sc;
        g_shift[c] = beta[c] - m * sc;
    }
}

// ---------------- bias3' = shift @ W3 partials, then + b3 ----------------
__global__ __launch_bounds__(256) void bias_mv(const float* __restrict__ W, int N)
{
    const int n = blockIdx.x * 256 + threadIdx.x;
    const int k0 = blockIdx.y * 128;
    float s = 0.f;
#pragma unroll 4
    for (int k = k0; k < k0 + 128; ++k)
        s = fmaf(g_shift[k], W[(size_t)k * N + n], s);
    g_psum[blockIdx.y * N + n] = s;
}
__global__ __launch_bounds__(256) void bias_fin(const float* __restrict__ b, int N)
{
    const int n = blockIdx.x * 256 + threadIdx.x;
    float s = b[n];
#pragma unroll
    for (int i = 0; i < 16; ++i) s += g_psum[i * N + n];
    g_bias[n] = s;
}

// ---------------- launch ----------------
extern "C" void kernel_launch(void* const* d_in, const int* in_sizes, int n_in,
                              void* d_out, int out_size)
{
    const float* ft0   = (const float*)d_in[1];
    const float* ft1   = (const float*)d_in[2];
    const float* ft2   = (const float*)d_in[3];
    const float* key   = (const float*)d_in[4];
    const float* W1    = (const float*)d_in[5];
    const float* g1    = (const float*)d_in[7];
    const float* beta1 = (const float*)d_in[8];
    const float* W2    = (const float*)d_in[9];
    const float* g2    = (const float*)d_in[11];
    const float* beta2 = (const float*)d_in[12];
    const float* W3    = (const float*)d_in[13];
    const float* b3    = (const float*)d_in[14];
    const float* We    = (const float*)d_in[15];
    const float* bE    = (const float*)d_in[16];

    float* out     = (float*)d_out;
    float* aligned = out;
    float* extend  = aligned + (size_t)BATCH * CH_H;
    float* ftall   = extend  + (size_t)BATCH * DIM;

    __half *Ah, *Ah2, *Bh;
    float *scaleP, *biasP;
    cudaGetSymbolAddress((void**)&Ah, g_Ah);
    cudaGetSymbolAddress((void**)&Ah2, g_Ah2);
    cudaGetSymbolAddress((void**)&Bh, g_Bh);
    cudaGetSymbolAddress((void**)&scaleP, g_scale);
    cudaGetSymbolAddress((void**)&biasP, g_bias);

    cudaFuncSetAttribute(gemm_mma<M_BIASRELU>,  cudaFuncAttributeMaxDynamicSharedMemorySize, SMEM_GEMM);
    cudaFuncSetAttribute(gemm_mma<M_PACK>,      cudaFuncAttributeMaxDynamicSharedMemorySize, SMEM_GEMM);
    cudaFuncSetAttribute(gemm_mma<M_STATSPACK>, cudaFuncAttributeMaxDynamicSharedMemorySize, SMEM_GEMM);

    const int MT = BATCH / BM;  // 64

    // 1) score + reweight + pack A1 (fp16) ; ft_all output
    score_pack<<<BATCH, 512>>>(ft0, ft1, ft2, key, ftall, Ah);

    // 2) layer 1 (K=6144): raw y1 -> fp16 Ah2 + fused stats
    pack_W_t<<<dim3(DIM / 32, CH_H / 32), 256>>>(W1, Bh, DIM, CH_H, nullptr);
    gemm_mma<M_STATSPACK><<<dim3(CH_H / BN, MT), 256, SMEM_GEMM>>>(
        Ah, Bh, nullptr, nullptr, Ah2, CH_H, DIM);
    colstats_final<<<CH_H / 32, 256>>>(g1, beta1, CH_H, 1.0f / BATCH);

    // 3) layer 2 (K=2048): W2 scaled by s1 rows; raw y2 -> fp16 Ah + fused stats
    pack_W_t<<<dim3(CH_H / 32, CH_H / 32), 256>>>(W2, Bh, CH_H, CH_H, scaleP);
    gemm_mma<M_STATSPACK><<<dim3(CH_H / BN, MT), 256, SMEM_GEMM>>>(
        Ah2, Bh, nullptr, nullptr, Ah, CH_H, CH_H);
    colstats_final<<<CH_H / 32, 256>>>(g2, beta2, CH_H, 1.0f / BATCH);

    // 4) layer 3: W3 scaled by s2 rows; bias3' = t2 @ W3 + b3; relu; dual write
    pack_W_t<<<dim3(CH_H / 32, CH_H / 32), 256>>>(W3, Bh, CH_H, CH_H, scaleP);
    bias_mv<<<dim3(CH_H / 256, 16), 256>>>(W3, CH_H);
    bias_fin<<<CH_H / 256, 256>>>(b3, CH_H);
    gemm_mma<M_PACK><<<dim3(CH_H / BN, MT), 256, SMEM_GEMM>>>(
        Ah, Bh, biasP, aligned, Ah2, CH_H, CH_H);

    // 5) extend = relu(aligned @ We + bE), input = Ah2
    pack_W_t<<<dim3(CH_H / 32, DIM / 32), 256>>>(We, Bh, CH_H, DIM, nullptr);
    gemm_mma<M_BIASRELU><<<dim3(DIM / BN, MT), 256, SMEM_GEMM>>>(
        Ah2, Bh, bE, extend, nullptr, DIM, CH_H);
}